// round 2
// baseline (speedup 1.0000x reference)
#include <cuda_runtime.h>

// Problem constants
#define BN   256      // batch
#define CN   1024     // channels
#define HW   169      // 13*13 spatial positions
#define GRID_W 13
#define SPLIT 2       // spatial splits per batch -> 512 blocks
#define Z_CONST 17.079468445347132f   // exp(log(2*pi)+1) = 2*pi*e
#define EPS_CONST 1e-6f

// Per-(b, split, moment, channel) partials. 256*2*5*1024 floats = 10.5 MB.
__device__ float g_part[BN * SPLIT * 5 * CN];
// Per-batch det sums.
__device__ float g_bsum[BN];

// ---------------------------------------------------------------------------
// Kernel 1: streaming softmax + moment accumulation.
// grid = BN*SPLIT = 512 blocks, 256 threads. Thread t owns channels [4t,4t+4).
// Processes 2 positions per iteration (2 independent shfl chains, 1 barrier).
// No atomics: plain stores to g_part.
// ---------------------------------------------------------------------------
__global__ __launch_bounds__(256, 4) void accum_kernel(const float* __restrict__ x) {
    const int b    = blockIdx.x >> 1;
    const int sp   = blockIdx.x & 1;
    const int p0   = sp ? 85 : 0;          // split 169 -> 85 + 84
    const int p1   = sp ? HW : 85;
    const int tid  = threadIdx.x;
    const int wid  = tid >> 5;
    const int lane = tid & 31;
    const int c4   = tid << 2;

    __shared__ float red[2][2][8];         // [buf][pos-in-pair][warp]

    const float4* __restrict__ xb = (const float4*)(x + (size_t)b * HW * CN);

    float S[4]   = {0.f, 0.f, 0.f, 0.f};
    float Sx[4]  = {0.f, 0.f, 0.f, 0.f};
    float Sy[4]  = {0.f, 0.f, 0.f, 0.f};
    float Sxx[4] = {0.f, 0.f, 0.f, 0.f};
    float Syy[4] = {0.f, 0.f, 0.f, 0.f};

    int buf = 0;
    for (int p = p0; p < p1; p += 2) {
        const bool pairB = (p + 1 < p1);

        float4 A = xb[(size_t)p * 256 + tid];
        float4 B = pairB ? xb[(size_t)(p + 1) * 256 + tid] : A;

        float ea0 = __expf(A.x), ea1 = __expf(A.y);
        float ea2 = __expf(A.z), ea3 = __expf(A.w);
        float eb0 = __expf(B.x), eb1 = __expf(B.y);
        float eb2 = __expf(B.z), eb3 = __expf(B.w);

        float pa = (ea0 + ea1) + (ea2 + ea3);
        float pb = (eb0 + eb1) + (eb2 + eb3);
        // two interleaved warp reductions (independent chains)
#pragma unroll
        for (int m = 16; m > 0; m >>= 1) {
            pa += __shfl_xor_sync(0xffffffffu, pa, m);
            pb += __shfl_xor_sync(0xffffffffu, pb, m);
        }
        if (lane == 0) { red[buf][0][wid] = pa; red[buf][1][wid] = pb; }
        __syncthreads();

        const float* rA = red[buf][0];
        const float* rB = red[buf][1];
        float denA = ((rA[0] + rA[1]) + (rA[2] + rA[3]))
                   + ((rA[4] + rA[5]) + (rA[6] + rA[7]));
        float denB = ((rB[0] + rB[1]) + (rB[2] + rB[3]))
                   + ((rB[4] + rB[5]) + (rB[6] + rB[7]));
        float invA = __fdividef(1.0f, denA);
        float invB = __fdividef(1.0f, denB);

        // position A weights
        {
            int h = p / GRID_W, w = p - h * GRID_W;
            float wx = (float)(h + 1), wy = (float)(w + 1);
            float w1 = invA * wx, w2 = invA * wy;
            float w3 = w1 * wx,   w4 = w2 * wy;
            float e[4] = {ea0, ea1, ea2, ea3};
#pragma unroll
            for (int j = 0; j < 4; ++j) {
                S[j]   = fmaf(invA, e[j], S[j]);
                Sx[j]  = fmaf(w1,   e[j], Sx[j]);
                Sy[j]  = fmaf(w2,   e[j], Sy[j]);
                Sxx[j] = fmaf(w3,   e[j], Sxx[j]);
                Syy[j] = fmaf(w4,   e[j], Syy[j]);
            }
        }
        // position B weights
        if (pairB) {
            int q = p + 1;
            int h = q / GRID_W, w = q - h * GRID_W;
            float wx = (float)(h + 1), wy = (float)(w + 1);
            float w1 = invB * wx, w2 = invB * wy;
            float w3 = w1 * wx,   w4 = w2 * wy;
            float e[4] = {eb0, eb1, eb2, eb3};
#pragma unroll
            for (int j = 0; j < 4; ++j) {
                S[j]   = fmaf(invB, e[j], S[j]);
                Sx[j]  = fmaf(w1,   e[j], Sx[j]);
                Sy[j]  = fmaf(w2,   e[j], Sy[j]);
                Sxx[j] = fmaf(w3,   e[j], Sxx[j]);
                Syy[j] = fmaf(w4,   e[j], Syy[j]);
            }
        }
        buf ^= 1;
    }

    // Plain coalesced stores of block partials: [B][SPLIT][5][CN]
    float* gp = g_part + ((size_t)(b * SPLIT + sp) * 5) * CN;
    *(float4*)(gp + 0 * CN + c4) = *(float4*)S;
    *(float4*)(gp + 1 * CN + c4) = *(float4*)Sx;
    *(float4*)(gp + 2 * CN + c4) = *(float4*)Sy;
    *(float4*)(gp + 3 * CN + c4) = *(float4*)Sxx;
    *(float4*)(gp + 4 * CN + c4) = *(float4*)Syy;
}

// ---------------------------------------------------------------------------
// Kernel 2: per-(b,c) determinant + per-batch reduction -> g_bsum[b].
// grid = BN blocks, 256 threads; thread handles 4 channels.
// ---------------------------------------------------------------------------
__global__ __launch_bounds__(256) void final_kernel() {
    const int b   = blockIdx.x;
    const int tid = threadIdx.x;
    const int c4  = tid << 2;
    const float* g0 = g_part + ((size_t)(b * SPLIT + 0) * 5) * CN;
    const float* g1 = g_part + ((size_t)(b * SPLIT + 1) * 5) * CN;

    float m[5][4];
#pragma unroll
    for (int k = 0; k < 5; ++k) {
        float4 a = *(const float4*)(g0 + k * CN + c4);
        float4 c = *(const float4*)(g1 + k * CN + c4);
        m[k][0] = a.x + c.x; m[k][1] = a.y + c.y;
        m[k][2] = a.z + c.z; m[k][3] = a.w + c.w;
    }

    float acc = 0.0f;
#pragma unroll
    for (int j = 0; j < 4; ++j) {
        float s     = m[0][j] + EPS_CONST;
        float inv_s = 1.0f / s;
        float mx    = m[1][j] * inv_s;
        float my    = m[2][j] * inv_s;
        float xnum  = m[3][j] - 2.0f * mx * m[1][j] + mx * mx * m[0][j];
        float ynum  = m[4][j] - 2.0f * my * m[2][j] + my * my * m[0][j];
        float x_var = xnum * inv_s * (1.0f / 169.0f);
        float y_var = ynum * inv_s * (1.0f / 169.0f);
        float d     = x_var + y_var;
        acc = fmaf(d * d, Z_CONST, acc);
    }

#pragma unroll
    for (int msk = 16; msk > 0; msk >>= 1)
        acc += __shfl_xor_sync(0xffffffffu, acc, msk);

    __shared__ float wsum[8];
    if ((tid & 31) == 0) wsum[tid >> 5] = acc;
    __syncthreads();
    if (tid == 0) {
        g_bsum[b] = ((wsum[0] + wsum[1]) + (wsum[2] + wsum[3]))
                  + ((wsum[4] + wsum[5]) + (wsum[6] + wsum[7]));
    }
}

// ---------------------------------------------------------------------------
// Kernel 3: reduce 256 batch sums -> scalar output (no atomics, no init).
// ---------------------------------------------------------------------------
__global__ void final2_kernel(float* __restrict__ out) {
    const int tid = threadIdx.x;
    float v = g_bsum[tid];
#pragma unroll
    for (int msk = 16; msk > 0; msk >>= 1)
        v += __shfl_xor_sync(0xffffffffu, v, msk);
    __shared__ float wsum[8];
    if ((tid & 31) == 0) wsum[tid >> 5] = v;
    __syncthreads();
    if (tid == 0) {
        float t = ((wsum[0] + wsum[1]) + (wsum[2] + wsum[3]))
                + ((wsum[4] + wsum[5]) + (wsum[6] + wsum[7]));
        out[0] = t * (1.0f / (float)(BN * CN));
    }
}

// ---------------------------------------------------------------------------
extern "C" void kernel_launch(void* const* d_in, const int* in_sizes, int n_in,
                              void* d_out, int out_size) {
    const float* x = (const float*)d_in[0];
    float* out = (float*)d_out;

    accum_kernel<<<BN * SPLIT, 256>>>(x);
    final_kernel<<<BN, 256>>>();
    final2_kernel<<<1, 256>>>(out);
}

// round 3
// speedup vs baseline: 1.1757x; 1.1757x over previous
#include <cuda_runtime.h>

// Problem constants
#define BN   256      // batch
#define CN   1024     // channels
#define HW   169      // 13*13 spatial positions
#define GRID_W 13
#define SPLIT 4       // spatial splits per batch -> 1024 blocks
#define Z_CONST 17.079468445347132f   // exp(log(2*pi)+1) = 2*pi*e
#define EPS_CONST 1e-6f

// Per-(b, split, moment, channel) partials. 256*4*5*1024 floats = 21 MB.
__device__ float g_part[BN * SPLIT * 5 * CN];
// Per-batch det sums.
__device__ float g_bsum[BN];

__device__ __forceinline__ float4 ldcs4(const float4* p) {
    return __ldcs(p);
}

// ---------------------------------------------------------------------------
// Kernel 1: streaming softmax + moments, 3-stage software pipeline.
// grid = BN*SPLIT = 1024 blocks, 256 threads, thread t owns channels [4t,4t+4).
// Pipeline per iteration k:
//   - load raw x for pair k+1            (consumed next iter -> DRAM latency hidden)
//   - exp + warp-reduce + smem for pair k
//   - FMA-accumulate pair k-1            (denoms from smem written last iter)
//   - one __syncthreads (double-buffered smem)
// ---------------------------------------------------------------------------
__global__ __launch_bounds__(256, 4) void accum_kernel(const float* __restrict__ x) {
    const int b    = blockIdx.x >> 2;
    const int sp   = blockIdx.x & 3;
    const int p0   = (sp * HW) >> 2;           // 0,42,84,126
    const int p1   = ((sp + 1) * HW) >> 2;     // 42,84,126,169
    const int tid  = threadIdx.x;
    const int wid  = tid >> 5;
    const int lane = tid & 31;
    const int c4   = tid << 2;

    __shared__ float red[2][2][8];             // [buf][pos-in-pair][warp]

    const float4* __restrict__ xb = (const float4*)(x + (size_t)b * HW * CN);

    float S[4]   = {0.f, 0.f, 0.f, 0.f};
    float Sx[4]  = {0.f, 0.f, 0.f, 0.f};
    float Sy[4]  = {0.f, 0.f, 0.f, 0.f};
    float Sxx[4] = {0.f, 0.f, 0.f, 0.f};
    float Syy[4] = {0.f, 0.f, 0.f, 0.f};

    const int np = (p1 - p0 + 1) >> 1;         // number of position pairs (21/22)

    // ---- prologue: load pair 0 (clamp odd tail: B falls back to A's row) ----
    float4 A = ldcs4(xb + (size_t)p0 * 256 + tid);
    float4 B = (p0 + 1 < p1) ? ldcs4(xb + (size_t)(p0 + 1) * 256 + tid) : A;

    float pea0=0, pea1=0, pea2=0, pea3=0;      // prev-pair exps (A)
    float peb0=0, peb1=0, peb2=0, peb3=0;      // prev-pair exps (B)

    for (int k = 0; k < np; ++k) {
        // ---- Stage L: prefetch pair k+1 ----
        float4 An = A, Bn = B;
        {
            const int pn = p0 + 2 * (k + 1);
            if (k + 1 < np) {
                An = ldcs4(xb + (size_t)pn * 256 + tid);
                Bn = (pn + 1 < p1) ? ldcs4(xb + (size_t)(pn + 1) * 256 + tid) : An;
            }
        }

        // ---- Stage E: exps + partial sums for pair k ----
        float ea0 = __expf(A.x), ea1 = __expf(A.y);
        float ea2 = __expf(A.z), ea3 = __expf(A.w);
        float eb0 = __expf(B.x), eb1 = __expf(B.y);
        float eb2 = __expf(B.z), eb3 = __expf(B.w);

        float pa = (ea0 + ea1) + (ea2 + ea3);
        float pb = (eb0 + eb1) + (eb2 + eb3);
#pragma unroll
        for (int m = 16; m > 0; m >>= 1) {
            pa += __shfl_xor_sync(0xffffffffu, pa, m);
            pb += __shfl_xor_sync(0xffffffffu, pb, m);
        }
        if (lane == 0) { red[k & 1][0][wid] = pa; red[k & 1][1][wid] = pb; }

        // ---- Stage F: accumulate pair k-1 (denoms ready since last barrier) ----
        if (k >= 1) {
            const float* rA = red[(k - 1) & 1][0];
            const float* rB = red[(k - 1) & 1][1];
            float denA = ((rA[0] + rA[1]) + (rA[2] + rA[3]))
                       + ((rA[4] + rA[5]) + (rA[6] + rA[7]));
            float denB = ((rB[0] + rB[1]) + (rB[2] + rB[3]))
                       + ((rB[4] + rB[5]) + (rB[6] + rB[7]));
            float invA = __fdividef(1.0f, denA);
            float invB = __fdividef(1.0f, denB);

            const int pA = p0 + 2 * (k - 1);
            {
                int h = pA / GRID_W, w = pA - h * GRID_W;
                float wx = (float)(h + 1), wy = (float)(w + 1);
                float w1 = invA * wx, w2 = invA * wy;
                float w3 = w1 * wx,   w4 = w2 * wy;
                float e[4] = {pea0, pea1, pea2, pea3};
#pragma unroll
                for (int j = 0; j < 4; ++j) {
                    S[j]   = fmaf(invA, e[j], S[j]);
                    Sx[j]  = fmaf(w1,   e[j], Sx[j]);
                    Sy[j]  = fmaf(w2,   e[j], Sy[j]);
                    Sxx[j] = fmaf(w3,   e[j], Sxx[j]);
                    Syy[j] = fmaf(w4,   e[j], Syy[j]);
                }
            }
            if (pA + 1 < p1) {
                int q = pA + 1;
                int h = q / GRID_W, w = q - h * GRID_W;
                float wx = (float)(h + 1), wy = (float)(w + 1);
                float w1 = invB * wx, w2 = invB * wy;
                float w3 = w1 * wx,   w4 = w2 * wy;
                float e[4] = {peb0, peb1, peb2, peb3};
#pragma unroll
                for (int j = 0; j < 4; ++j) {
                    S[j]   = fmaf(invB, e[j], S[j]);
                    Sx[j]  = fmaf(w1,   e[j], Sx[j]);
                    Sy[j]  = fmaf(w2,   e[j], Sy[j]);
                    Sxx[j] = fmaf(w3,   e[j], Sxx[j]);
                    Syy[j] = fmaf(w4,   e[j], Syy[j]);
                }
            }
        }

        __syncthreads();

        // rotate pipeline registers
        pea0 = ea0; pea1 = ea1; pea2 = ea2; pea3 = ea3;
        peb0 = eb0; peb1 = eb1; peb2 = eb2; peb3 = eb3;
        A = An; B = Bn;
    }

    // ---- epilogue: accumulate final pair np-1 ----
    {
        const int k = np;
        const float* rA = red[(k - 1) & 1][0];
        const float* rB = red[(k - 1) & 1][1];
        float denA = ((rA[0] + rA[1]) + (rA[2] + rA[3]))
                   + ((rA[4] + rA[5]) + (rA[6] + rA[7]));
        float denB = ((rB[0] + rB[1]) + (rB[2] + rB[3]))
                   + ((rB[4] + rB[5]) + (rB[6] + rB[7]));
        float invA = __fdividef(1.0f, denA);
        float invB = __fdividef(1.0f, denB);

        const int pA = p0 + 2 * (k - 1);
        {
            int h = pA / GRID_W, w = pA - h * GRID_W;
            float wx = (float)(h + 1), wy = (float)(w + 1);
            float w1 = invA * wx, w2 = invA * wy;
            float w3 = w1 * wx,   w4 = w2 * wy;
            float e[4] = {pea0, pea1, pea2, pea3};
#pragma unroll
            for (int j = 0; j < 4; ++j) {
                S[j]   = fmaf(invA, e[j], S[j]);
                Sx[j]  = fmaf(w1,   e[j], Sx[j]);
                Sy[j]  = fmaf(w2,   e[j], Sy[j]);
                Sxx[j] = fmaf(w3,   e[j], Sxx[j]);
                Syy[j] = fmaf(w4,   e[j], Syy[j]);
            }
        }
        if (pA + 1 < p1) {
            int q = pA + 1;
            int h = q / GRID_W, w = q - h * GRID_W;
            float wx = (float)(h + 1), wy = (float)(w + 1);
            float w1 = invB * wx, w2 = invB * wy;
            float w3 = w1 * wx,   w4 = w2 * wy;
            float e[4] = {peb0, peb1, peb2, peb3};
#pragma unroll
            for (int j = 0; j < 4; ++j) {
                S[j]   = fmaf(invB, e[j], S[j]);
                Sx[j]  = fmaf(w1,   e[j], Sx[j]);
                Sy[j]  = fmaf(w2,   e[j], Sy[j]);
                Sxx[j] = fmaf(w3,   e[j], Sxx[j]);
                Syy[j] = fmaf(w4,   e[j], Syy[j]);
            }
        }
    }

    // ---- coalesced partial stores: [B][SPLIT][5][CN] ----
    float* gp = g_part + ((size_t)(b * SPLIT + sp) * 5) * CN;
    *(float4*)(gp + 0 * CN + c4) = *(float4*)S;
    *(float4*)(gp + 1 * CN + c4) = *(float4*)Sx;
    *(float4*)(gp + 2 * CN + c4) = *(float4*)Sy;
    *(float4*)(gp + 3 * CN + c4) = *(float4*)Sxx;
    *(float4*)(gp + 4 * CN + c4) = *(float4*)Syy;
}

// ---------------------------------------------------------------------------
// Kernel 2: per-(b,c) determinant + per-batch reduction -> g_bsum[b].
// ---------------------------------------------------------------------------
__global__ __launch_bounds__(256) void final_kernel() {
    const int b   = blockIdx.x;
    const int tid = threadIdx.x;
    const int c4  = tid << 2;

    float m[5][4];
#pragma unroll
    for (int k = 0; k < 5; ++k)
#pragma unroll
        for (int j = 0; j < 4; ++j) m[k][j] = 0.0f;

#pragma unroll
    for (int s = 0; s < SPLIT; ++s) {
        const float* gs = g_part + ((size_t)(b * SPLIT + s) * 5) * CN;
#pragma unroll
        for (int k = 0; k < 5; ++k) {
            float4 a = *(const float4*)(gs + k * CN + c4);
            m[k][0] += a.x; m[k][1] += a.y; m[k][2] += a.z; m[k][3] += a.w;
        }
    }

    float acc = 0.0f;
#pragma unroll
    for (int j = 0; j < 4; ++j) {
        float s     = m[0][j] + EPS_CONST;
        float inv_s = 1.0f / s;
        float mx    = m[1][j] * inv_s;
        float my    = m[2][j] * inv_s;
        float xnum  = m[3][j] - 2.0f * mx * m[1][j] + mx * mx * m[0][j];
        float ynum  = m[4][j] - 2.0f * my * m[2][j] + my * my * m[0][j];
        float x_var = xnum * inv_s * (1.0f / 169.0f);
        float y_var = ynum * inv_s * (1.0f / 169.0f);
        float d     = x_var + y_var;
        acc = fmaf(d * d, Z_CONST, acc);
    }

#pragma unroll
    for (int msk = 16; msk > 0; msk >>= 1)
        acc += __shfl_xor_sync(0xffffffffu, acc, msk);

    __shared__ float wsum[8];
    if ((tid & 31) == 0) wsum[tid >> 5] = acc;
    __syncthreads();
    if (tid == 0) {
        g_bsum[b] = ((wsum[0] + wsum[1]) + (wsum[2] + wsum[3]))
                  + ((wsum[4] + wsum[5]) + (wsum[6] + wsum[7]));
    }
}

// ---------------------------------------------------------------------------
// Kernel 3: reduce 256 batch sums -> scalar output.
// ---------------------------------------------------------------------------
__global__ void final2_kernel(float* __restrict__ out) {
    const int tid = threadIdx.x;
    float v = g_bsum[tid];
#pragma unroll
    for (int msk = 16; msk > 0; msk >>= 1)
        v += __shfl_xor_sync(0xffffffffu, v, msk);
    __shared__ float wsum[8];
    if ((tid & 31) == 0) wsum[tid >> 5] = v;
    __syncthreads();
    if (tid == 0) {
        float t = ((wsum[0] + wsum[1]) + (wsum[2] + wsum[3]))
                + ((wsum[4] + wsum[5]) + (wsum[6] + wsum[7]));
        out[0] = t * (1.0f / (float)(BN * CN));
    }
}

// ---------------------------------------------------------------------------
extern "C" void kernel_launch(void* const* d_in, const int* in_sizes, int n_in,
                              void* d_out, int out_size) {
    const float* x = (const float*)d_in[0];
    float* out = (float*)d_out;

    accum_kernel<<<BN * SPLIT, 256>>>(x);
    final_kernel<<<BN, 256>>>();
    final2_kernel<<<1, 256>>>(out);
}

// round 4
// speedup vs baseline: 1.2806x; 1.0893x over previous
#include <cuda_runtime.h>

// Problem constants
#define BN   256
#define CN   1024
#define HW   169      // 13*13
#define SPLIT 4       // -> 1024 blocks
#define Z_CONST 17.079468445347132f   // 2*pi*e
#define EPS_CONST 1e-6f

// Per-(b, split, moment, channel) partials, 4 moments: S, Sx, Sy, Sr=S(wx^2+wy^2).
// 256*4*4*1024 floats = 16.8 MB.
__device__ float g_part[BN * SPLIT * 4 * CN];

// ---------------------------------------------------------------------------
// Kernel 1: streaming softmax + moments, 3-stage pipeline, 1 position/iter.
// grid = 1024 blocks x 256 thr; thread t owns channels [4t,4t+4).
// ---------------------------------------------------------------------------
__global__ __launch_bounds__(256, 5) void accum_kernel(const float* __restrict__ x,
                                                       float* __restrict__ out) {
    if (blockIdx.x == 0 && threadIdx.x == 0) out[0] = 0.0f;  // init for final atomics

    const int b    = blockIdx.x >> 2;
    const int sp   = blockIdx.x & 3;
    const int p0   = (sp * HW) >> 2;           // 0,42,84,126
    const int p1   = ((sp + 1) * HW) >> 2;     // 42,84,126,169
    const int n    = p1 - p0;
    const int tid  = threadIdx.x;
    const int wid  = tid >> 5;
    const int lane = tid & 31;

    __shared__ __align__(16) float red[2][8];

    const float4* __restrict__ xb = (const float4*)(x + (size_t)b * HW * CN) + tid;

    float S[4]  = {0.f, 0.f, 0.f, 0.f};
    float Sx[4] = {0.f, 0.f, 0.f, 0.f};
    float Sy[4] = {0.f, 0.f, 0.f, 0.f};
    float Sr[4] = {0.f, 0.f, 0.f, 0.f};

    // weights for the (delayed) F-stage position, carried incrementally
    const int fh0 = p0 / 13;
    float wx = (float)(fh0 + 1);
    float wy = (float)(p0 - fh0 * 13 + 1);

    float4 cur = __ldcs(xb + (size_t)p0 * 256);
    float pe0 = 0.f, pe1 = 0.f, pe2 = 0.f, pe3 = 0.f;

    for (int k = 0; k < n; ++k) {
        // ---- Stage L: prefetch position k+1 ----
        float4 nxt = cur;
        if (k + 1 < n) nxt = __ldcs(xb + (size_t)(p0 + k + 1) * 256);

        // ---- Stage E: exps + warp partial for position k ----
        float e0 = __expf(cur.x), e1 = __expf(cur.y);
        float e2 = __expf(cur.z), e3 = __expf(cur.w);
        float pa = (e0 + e1) + (e2 + e3);
#pragma unroll
        for (int m = 16; m > 0; m >>= 1)
            pa += __shfl_xor_sync(0xffffffffu, pa, m);
        if (lane == 0) red[k & 1][wid] = pa;

        // ---- Stage F: accumulate position k-1 (denom published at last bar) ----
        if (k >= 1) {
            const float4* rp = (const float4*)red[(k - 1) & 1];
            float4 ra = rp[0], rb = rp[1];
            float den = ((ra.x + ra.y) + (ra.z + ra.w))
                      + ((rb.x + rb.y) + (rb.z + rb.w));
            float inv = __fdividef(1.0f, den);
            float w1  = inv * wx;
            float w2  = inv * wy;
            float wr  = fmaf(wx, wx, wy * wy) * inv;
            float e[4] = {pe0, pe1, pe2, pe3};
#pragma unroll
            for (int j = 0; j < 4; ++j) {
                S[j]  = fmaf(inv, e[j], S[j]);
                Sx[j] = fmaf(w1,  e[j], Sx[j]);
                Sy[j] = fmaf(w2,  e[j], Sy[j]);
                Sr[j] = fmaf(wr,  e[j], Sr[j]);
            }
            // advance F-position weights
            wy += 1.0f;
            if (wy > 13.0f) { wy = 1.0f; wx += 1.0f; }
        }

        __syncthreads();

        pe0 = e0; pe1 = e1; pe2 = e2; pe3 = e3;
        cur = nxt;
    }

    // ---- epilogue: accumulate final position (k = n) ----
    {
        const float4* rp = (const float4*)red[(n - 1) & 1];
        float4 ra = rp[0], rb = rp[1];
        float den = ((ra.x + ra.y) + (ra.z + ra.w))
                  + ((rb.x + rb.y) + (rb.z + rb.w));
        float inv = __fdividef(1.0f, den);
        float w1  = inv * wx;
        float w2  = inv * wy;
        float wr  = fmaf(wx, wx, wy * wy) * inv;
        float e[4] = {pe0, pe1, pe2, pe3};
#pragma unroll
        for (int j = 0; j < 4; ++j) {
            S[j]  = fmaf(inv, e[j], S[j]);
            Sx[j] = fmaf(w1,  e[j], Sx[j]);
            Sy[j] = fmaf(w2,  e[j], Sy[j]);
            Sr[j] = fmaf(wr,  e[j], Sr[j]);
        }
    }

    // ---- coalesced partial stores: [B][SPLIT][4][CN] ----
    const int c4 = tid << 2;
    float* gp = g_part + ((size_t)(b * SPLIT + sp) * 4) * CN;
    *(float4*)(gp + 0 * CN + c4) = *(float4*)S;
    *(float4*)(gp + 1 * CN + c4) = *(float4*)Sx;
    *(float4*)(gp + 2 * CN + c4) = *(float4*)Sy;
    *(float4*)(gp + 3 * CN + c4) = *(float4*)Sr;
}

// ---------------------------------------------------------------------------
// Kernel 2: sum splits, per-(b,c) det, reduce, atomicAdd scalar.
// grid = BN blocks, 256 threads; thread handles 4 channels.
// ---------------------------------------------------------------------------
__global__ __launch_bounds__(256) void final_kernel(float* __restrict__ out) {
    const int b   = blockIdx.x;
    const int tid = threadIdx.x;
    const int c4  = tid << 2;

    float m0[4] = {0,0,0,0}, m1[4] = {0,0,0,0}, m2[4] = {0,0,0,0}, m3[4] = {0,0,0,0};
#pragma unroll
    for (int s = 0; s < SPLIT; ++s) {
        const float* gs = g_part + ((size_t)(b * SPLIT + s) * 4) * CN;
        float4 a0 = *(const float4*)(gs + 0 * CN + c4);
        float4 a1 = *(const float4*)(gs + 1 * CN + c4);
        float4 a2 = *(const float4*)(gs + 2 * CN + c4);
        float4 a3 = *(const float4*)(gs + 3 * CN + c4);
        m0[0] += a0.x; m0[1] += a0.y; m0[2] += a0.z; m0[3] += a0.w;
        m1[0] += a1.x; m1[1] += a1.y; m1[2] += a1.z; m1[3] += a1.w;
        m2[0] += a2.x; m2[1] += a2.y; m2[2] += a2.z; m2[3] += a2.w;
        m3[0] += a3.x; m3[1] += a3.y; m3[2] += a3.z; m3[3] += a3.w;
    }

    float acc = 0.0f;
#pragma unroll
    for (int j = 0; j < 4; ++j) {
        float s     = m0[j] + EPS_CONST;
        float inv_s = 1.0f / s;
        float mx    = m1[j] * inv_s;
        float my    = m2[j] * inv_s;
        // Sxx+Syy - 2(mx Sx + my Sy) + (mx^2+my^2) S
        float num   = m3[j] - 2.0f * (mx * m1[j] + my * m2[j])
                    + (mx * mx + my * my) * m0[j];
        float d     = num * inv_s * (1.0f / 169.0f);
        acc = fmaf(d * d, Z_CONST, acc);
    }

#pragma unroll
    for (int msk = 16; msk > 0; msk >>= 1)
        acc += __shfl_xor_sync(0xffffffffu, acc, msk);

    __shared__ float wsum[8];
    if ((tid & 31) == 0) wsum[tid >> 5] = acc;
    __syncthreads();
    if (tid == 0) {
        float t = ((wsum[0] + wsum[1]) + (wsum[2] + wsum[3]))
                + ((wsum[4] + wsum[5]) + (wsum[6] + wsum[7]));
        atomicAdd(out, t * (1.0f / (float)(BN * CN)));
    }
}

// ---------------------------------------------------------------------------
extern "C" void kernel_launch(void* const* d_in, const int* in_sizes, int n_in,
                              void* d_out, int out_size) {
    const float* x = (const float*)d_in[0];
    float* out = (float*)d_out;

    accum_kernel<<<BN * SPLIT, 256>>>(x, out);
    final_kernel<<<BN, 256>>>(out);
}